// round 3
// baseline (speedup 1.0000x reference)
#include <cuda_runtime.h>
#include <math.h>

#define BATCH 64
#define MOLA  50
#define PROA  500
#define HID   32
#define HEADS 8
#define NMOL  (BATCH * MOLA)          // 3200
#define NPRO  (BATCH * PROA)          // 32000
#define NPAIR ((size_t)NMOL * PROA)   // 1,600,000

// Scratch (allocation-free rule: __device__ globals)
__device__ float g_Amu [NMOL * HEADS];
__device__ float g_Asig[NMOL * HEADS];
__device__ float g_Pmu [NPRO * HEADS];
__device__ float g_Psig[NPRO * HEADS];
__device__ float g_ymol[NMOL * HEADS];

// ---------------------------------------------------------------------------
// Kernel 1: per-atom projections.
//   A_mu[m,h]  = b_mu[h]  + sum_k mol[m,k] * W_mu[k,h]        (mol rows of W)
//   P_mu[j,h]  =            sum_k (pro[j,k]*spat[j,k]) * W_mu[32+k,h]
//   (same for sigma)
// ---------------------------------------------------------------------------
__global__ void proj_kernel(const float* __restrict__ mol_feats,
                            const float* __restrict__ pro_feats,
                            const float* __restrict__ spat,
                            const float* __restrict__ Wsig,
                            const float* __restrict__ bsig,
                            const float* __restrict__ Wmu,
                            const float* __restrict__ bmu)
{
    __shared__ float sWmu[2 * HID * HEADS];   // 512 floats
    __shared__ float sWsig[2 * HID * HEADS];
    for (int i = threadIdx.x; i < 2 * HID * HEADS; i += blockDim.x) {
        sWmu[i]  = Wmu[i];
        sWsig[i] = Wsig[i];
    }
    __syncthreads();

    int r = blockIdx.x * blockDim.x + threadIdx.x;
    float f[HID];
    if (r < NMOL) {
        #pragma unroll
        for (int k = 0; k < HID; k++) f[k] = mol_feats[r * HID + k];
        #pragma unroll
        for (int h = 0; h < HEADS; h++) {
            float am = bmu[h], as = bsig[h];
            #pragma unroll
            for (int k = 0; k < HID; k++) {
                am = fmaf(f[k], sWmu [k * HEADS + h], am);
                as = fmaf(f[k], sWsig[k * HEADS + h], as);
            }
            g_Amu [r * HEADS + h] = am;
            g_Asig[r * HEADS + h] = as;
        }
    } else if (r < NMOL + NPRO) {
        int j = r - NMOL;
        #pragma unroll
        for (int k = 0; k < HID; k++)
            f[k] = pro_feats[j * HID + k] * spat[j * HID + k];
        #pragma unroll
        for (int h = 0; h < HEADS; h++) {
            float pm = 0.f, ps = 0.f;
            #pragma unroll
            for (int k = 0; k < HID; k++) {
                pm = fmaf(f[k], sWmu [(HID + k) * HEADS + h], pm);
                ps = fmaf(f[k], sWsig[(HID + k) * HEADS + h], ps);
            }
            g_Pmu [j * HEADS + h] = pm;
            g_Psig[j * HEADS + h] = ps;
        }
    }
}

// ---------------------------------------------------------------------------
// Kernel 2: per-pair mu/sigma + deterministic per-mol-atom sum of mu.
// One block per mol atom m (3200 blocks, 128 threads).
// Pair p = m*PROA + j0; pro atom index jg = (m/MOLA)*PROA + j0 (structured;
// the mol_index/pro_index input arrays are never read).
//   mu    = elu(x)+1.0 = x>0 ? x+1.0 : exp(x)
//   sigma = elu(x)+1.1 = x>0 ? x+1.1 : exp(x)+0.1
// ---------------------------------------------------------------------------
#define PAIR_THREADS 128

__global__ __launch_bounds__(PAIR_THREADS)
void pairs_kernel(float* __restrict__ out_mu, float* __restrict__ out_sig)
{
    const int m = blockIdx.x;
    const int b = m / MOLA;
    const int jbase = b * PROA;

    float am[HEADS], as_[HEADS];
    #pragma unroll
    for (int h = 0; h < HEADS; h++) {
        am[h]  = g_Amu [m * HEADS + h];
        as_[h] = g_Asig[m * HEADS + h];
    }

    float acc[HEADS];
    #pragma unroll
    for (int h = 0; h < HEADS; h++) acc[h] = 0.f;

    for (int j0 = threadIdx.x; j0 < PROA; j0 += PAIR_THREADS) {
        const int jg = jbase + j0;
        const float4 pm0 = *(const float4*)(g_Pmu  + jg * HEADS);
        const float4 pm1 = *(const float4*)(g_Pmu  + jg * HEADS + 4);
        const float4 ps0 = *(const float4*)(g_Psig + jg * HEADS);
        const float4 ps1 = *(const float4*)(g_Psig + jg * HEADS + 4);

        float xm[HEADS] = { am[0] + pm0.x, am[1] + pm0.y, am[2] + pm0.z, am[3] + pm0.w,
                            am[4] + pm1.x, am[5] + pm1.y, am[6] + pm1.z, am[7] + pm1.w };
        float xs[HEADS] = { as_[0] + ps0.x, as_[1] + ps0.y, as_[2] + ps0.z, as_[3] + ps0.w,
                            as_[4] + ps1.x, as_[5] + ps1.y, as_[6] + ps1.z, as_[7] + ps1.w };

        float mu[HEADS], sg[HEADS];
        #pragma unroll
        for (int h = 0; h < HEADS; h++) {
            mu[h] = (xm[h] > 0.f) ? (xm[h] + 1.0f) : expf(xm[h]);
            sg[h] = (xs[h] > 0.f) ? (xs[h] + 1.1f) : (expf(xs[h]) + 0.1f);
            acc[h] += mu[h];
        }

        const size_t p = (size_t)m * PROA + j0;
        float4* om = (float4*)(out_mu  + p * HEADS);
        float4* os = (float4*)(out_sig + p * HEADS);
        om[0] = make_float4(mu[0], mu[1], mu[2], mu[3]);
        om[1] = make_float4(mu[4], mu[5], mu[6], mu[7]);
        os[0] = make_float4(sg[0], sg[1], sg[2], sg[3]);
        os[1] = make_float4(sg[4], sg[5], sg[6], sg[7]);
    }

    // Deterministic reduction of acc[8]:
    //   stage 1: warp butterfly (in-register, 3 shuffle rounds after 2 fold rounds)
    #pragma unroll
    for (int s = 16; s > 0; s >>= 1) {
        #pragma unroll
        for (int h = 0; h < HEADS; h++)
            acc[h] += __shfl_xor_sync(0xFFFFFFFFu, acc[h], s);
    }
    //   stage 2: combine the 4 warp leaders through shared memory
    __shared__ float swarp[4][HEADS];
    const int wid = threadIdx.x >> 5;
    const int lid = threadIdx.x & 31;
    if (lid == 0) {
        #pragma unroll
        for (int h = 0; h < HEADS; h++) swarp[wid][h] = acc[h];
    }
    __syncthreads();
    if (threadIdx.x < HEADS) {
        float t = swarp[0][threadIdx.x] + swarp[1][threadIdx.x]
                + swarp[2][threadIdx.x] + swarp[3][threadIdx.x];
        g_ymol[m * HEADS + threadIdx.x] = t;
    }
}

// ---------------------------------------------------------------------------
// Kernel 3: batch head.  y[b] = elu((0.001*sum_mol ymol) @ W1 + b1) @ W2 + b2
// ---------------------------------------------------------------------------
__global__ void final_kernel(const float* __restrict__ W1, const float* __restrict__ b1,
                             const float* __restrict__ W2, const float* __restrict__ b2,
                             float* __restrict__ out_y)
{
    int b = threadIdx.x;
    if (b >= BATCH) return;
    float y[HEADS];
    #pragma unroll
    for (int h = 0; h < HEADS; h++) y[h] = 0.f;
    for (int m = 0; m < MOLA; m++) {
        #pragma unroll
        for (int h = 0; h < HEADS; h++)
            y[h] += g_ymol[(b * MOLA + m) * HEADS + h];
    }
    #pragma unroll
    for (int h = 0; h < HEADS; h++) y[h] *= 0.001f;

    float outv = b2[0];
    #pragma unroll
    for (int j = 0; j < 2 * HEADS; j++) {
        float t = b1[j];
        #pragma unroll
        for (int h = 0; h < HEADS; h++)
            t = fmaf(y[h], W1[h * (2 * HEADS) + j], t);
        t = (t > 0.f) ? t : expm1f(t);           // plain elu
        outv = fmaf(t, W2[j], outv);
    }
    out_y[b] = outv;
}

// ---------------------------------------------------------------------------
// Launch. Inputs (metadata order): mol_feats, pro_feats, spatial_feats,
// W_sigma, b_sigma, W_mu, b_mu, W1, b1, W2, b2, mol_index, pro_index, mol_batch.
// Indices are fully structured -> computed arithmetically, never read.
// Output: [mu (P*8) | sigma (P*8) | y (64)] float32.
// ---------------------------------------------------------------------------
extern "C" void kernel_launch(void* const* d_in, const int* in_sizes, int n_in,
                              void* d_out, int out_size)
{
    const float* mol_feats = (const float*)d_in[0];
    const float* pro_feats = (const float*)d_in[1];
    const float* spat      = (const float*)d_in[2];
    const float* Wsig      = (const float*)d_in[3];
    const float* bsig      = (const float*)d_in[4];
    const float* Wmu       = (const float*)d_in[5];
    const float* bmu       = (const float*)d_in[6];
    const float* W1        = (const float*)d_in[7];
    const float* b1        = (const float*)d_in[8];
    const float* W2        = (const float*)d_in[9];
    const float* b2        = (const float*)d_in[10];

    float* out_mu  = (float*)d_out;
    float* out_sig = out_mu + NPAIR * HEADS;
    float* out_y   = out_mu + 2 * NPAIR * HEADS;

    const int rows = NMOL + NPRO;
    proj_kernel<<<(rows + 255) / 256, 256>>>(mol_feats, pro_feats, spat,
                                             Wsig, bsig, Wmu, bmu);
    pairs_kernel<<<NMOL, PAIR_THREADS>>>(out_mu, out_sig);
    final_kernel<<<1, BATCH>>>(W1, b1, W2, b2, out_y);
}

// round 7
// speedup vs baseline: 1.1465x; 1.1465x over previous
#include <cuda_runtime.h>
#include <math.h>

#define BATCH 64
#define MOLA  50
#define PROA  500
#define HID   32
#define HEADS 8
#define NMOL  (BATCH * MOLA)          // 3200
#define NPRO  (BATCH * PROA)          // 32000
#define NPAIR ((size_t)NMOL * PROA)   // 1,600,000

// Scratch (allocation-free rule: __device__ globals)
__device__ float g_Amu [NMOL * HEADS];
__device__ float g_Asig[NMOL * HEADS];
__device__ float g_Pmu [NPRO * HEADS];
__device__ float g_Psig[NPRO * HEADS];
__device__ float g_ymol[NMOL * HEADS];

// ---------------------------------------------------------------------------
// Kernel 1: per-atom projections (spill-free rewrite).
// k-outer / h-inner with float4 feature chunks in flight; 16 live
// accumulators -> ~50 regs, no local-memory spills.
//   A_mu[m,h]  = b_mu[h]  + sum_k mol[m,k] * W_mu[k,h]
//   P_mu[j,h]  =            sum_k (pro[j,k]*spat[j,k]) * W_mu[32+k,h]
// ---------------------------------------------------------------------------
__global__ __launch_bounds__(256)
void proj_kernel(const float* __restrict__ mol_feats,
                 const float* __restrict__ pro_feats,
                 const float* __restrict__ spat,
                 const float* __restrict__ Wsig,
                 const float* __restrict__ bsig,
                 const float* __restrict__ Wmu,
                 const float* __restrict__ bmu)
{
    __shared__ float sWmu[2 * HID * HEADS];   // 512 floats each
    __shared__ float sWsig[2 * HID * HEADS];
    for (int i = threadIdx.x; i < 2 * HID * HEADS; i += blockDim.x) {
        sWmu[i]  = Wmu[i];
        sWsig[i] = Wsig[i];
    }
    __syncthreads();

    const int r = blockIdx.x * blockDim.x + threadIdx.x;
    if (r >= NMOL + NPRO) return;

    const bool isMol = (r < NMOL);
    const int  j     = isMol ? r : (r - NMOL);

    float accm[HEADS], accs[HEADS];
    #pragma unroll
    for (int h = 0; h < HEADS; h++) {
        accm[h] = isMol ? bmu[h]  : 0.f;
        accs[h] = isMol ? bsig[h] : 0.f;
    }

    // weight row offset: mol rows use W[0:32], pro rows use W[32:64]
    const float* wm = isMol ? sWmu  : (sWmu  + HID * HEADS);
    const float* ws = isMol ? sWsig : (sWsig + HID * HEADS);

    const float4* fsrc = isMol ? (const float4*)(mol_feats + (size_t)r * HID)
                               : (const float4*)(pro_feats + (size_t)j * HID);
    const float4* ssrc = isMol ? nullptr
                               : (const float4*)(spat + (size_t)j * HID);

    #pragma unroll
    for (int c = 0; c < HID / 4; c++) {
        float4 f4 = fsrc[c];
        if (!isMol) {
            float4 s4 = ssrc[c];
            f4.x *= s4.x; f4.y *= s4.y; f4.z *= s4.z; f4.w *= s4.w;
        }
        const float fv[4] = { f4.x, f4.y, f4.z, f4.w };
        #pragma unroll
        for (int e = 0; e < 4; e++) {
            const int k = c * 4 + e;
            #pragma unroll
            for (int h = 0; h < HEADS; h++) {
                accm[h] = fmaf(fv[e], wm[k * HEADS + h], accm[h]);
                accs[h] = fmaf(fv[e], ws[k * HEADS + h], accs[h]);
            }
        }
    }

    float* dm = isMol ? (g_Amu  + (size_t)r * HEADS) : (g_Pmu  + (size_t)j * HEADS);
    float* ds = isMol ? (g_Asig + (size_t)r * HEADS) : (g_Psig + (size_t)j * HEADS);
    ((float4*)dm)[0] = make_float4(accm[0], accm[1], accm[2], accm[3]);
    ((float4*)dm)[1] = make_float4(accm[4], accm[5], accm[6], accm[7]);
    ((float4*)ds)[0] = make_float4(accs[0], accs[1], accs[2], accs[3]);
    ((float4*)ds)[1] = make_float4(accs[4], accs[5], accs[6], accs[7]);
}

// ---------------------------------------------------------------------------
// Kernel 2: per-pair mu/sigma + deterministic per-mol-atom sum of mu.
// One block per mol atom m (3200 blocks, 128 threads).
// Pair p = m*PROA + j0; pro atom index jg = (m/MOLA)*PROA + j0 (structured;
// the mol_index/pro_index input arrays are never read).
//   mu    = elu(x)+1.0 = x>0 ? x+1.0 : exp(x)
//   sigma = elu(x)+1.1 = x>0 ? x+1.1 : exp(x)+0.1
// __expf (MUFU.EX2 path): rel err ~1e-7 per call, tolerance is 1e-3.
// ---------------------------------------------------------------------------
#define PAIR_THREADS 128

__global__ __launch_bounds__(PAIR_THREADS)
void pairs_kernel(float* __restrict__ out_mu, float* __restrict__ out_sig)
{
    const int m = blockIdx.x;
    const int b = m / MOLA;
    const int jbase = b * PROA;

    float am[HEADS], as_[HEADS];
    {
        const float4 a0 = ((const float4*)(g_Amu  + (size_t)m * HEADS))[0];
        const float4 a1 = ((const float4*)(g_Amu  + (size_t)m * HEADS))[1];
        const float4 s0 = ((const float4*)(g_Asig + (size_t)m * HEADS))[0];
        const float4 s1 = ((const float4*)(g_Asig + (size_t)m * HEADS))[1];
        am[0]=a0.x; am[1]=a0.y; am[2]=a0.z; am[3]=a0.w;
        am[4]=a1.x; am[5]=a1.y; am[6]=a1.z; am[7]=a1.w;
        as_[0]=s0.x; as_[1]=s0.y; as_[2]=s0.z; as_[3]=s0.w;
        as_[4]=s1.x; as_[5]=s1.y; as_[6]=s1.z; as_[7]=s1.w;
    }

    float acc[HEADS];
    #pragma unroll
    for (int h = 0; h < HEADS; h++) acc[h] = 0.f;

    for (int j0 = threadIdx.x; j0 < PROA; j0 += PAIR_THREADS) {
        const int jg = jbase + j0;
        const float4 pm0 = ((const float4*)(g_Pmu  + (size_t)jg * HEADS))[0];
        const float4 pm1 = ((const float4*)(g_Pmu  + (size_t)jg * HEADS))[1];
        const float4 ps0 = ((const float4*)(g_Psig + (size_t)jg * HEADS))[0];
        const float4 ps1 = ((const float4*)(g_Psig + (size_t)jg * HEADS))[1];

        const float xm[HEADS] = { am[0]+pm0.x, am[1]+pm0.y, am[2]+pm0.z, am[3]+pm0.w,
                                  am[4]+pm1.x, am[5]+pm1.y, am[6]+pm1.z, am[7]+pm1.w };
        const float xs[HEADS] = { as_[0]+ps0.x, as_[1]+ps0.y, as_[2]+ps0.z, as_[3]+ps0.w,
                                  as_[4]+ps1.x, as_[5]+ps1.y, as_[6]+ps1.z, as_[7]+ps1.w };

        float mu[HEADS], sg[HEADS];
        #pragma unroll
        for (int h = 0; h < HEADS; h++) {
            mu[h] = (xm[h] > 0.f) ? (xm[h] + 1.0f) : __expf(xm[h]);
            sg[h] = (xs[h] > 0.f) ? (xs[h] + 1.1f) : (__expf(xs[h]) + 0.1f);
            acc[h] += mu[h];
        }

        const size_t p = (size_t)m * PROA + j0;
        float4* om = (float4*)(out_mu  + p * HEADS);
        float4* os = (float4*)(out_sig + p * HEADS);
        om[0] = make_float4(mu[0], mu[1], mu[2], mu[3]);
        om[1] = make_float4(mu[4], mu[5], mu[6], mu[7]);
        os[0] = make_float4(sg[0], sg[1], sg[2], sg[3]);
        os[1] = make_float4(sg[4], sg[5], sg[6], sg[7]);
    }

    // Deterministic reduction of acc[8]: warp butterfly, then 4-warp combine.
    #pragma unroll
    for (int s = 16; s > 0; s >>= 1) {
        #pragma unroll
        for (int h = 0; h < HEADS; h++)
            acc[h] += __shfl_xor_sync(0xFFFFFFFFu, acc[h], s);
    }
    __shared__ float swarp[4][HEADS];
    const int wid = threadIdx.x >> 5;
    const int lid = threadIdx.x & 31;
    if (lid == 0) {
        #pragma unroll
        for (int h = 0; h < HEADS; h++) swarp[wid][h] = acc[h];
    }
    __syncthreads();
    if (threadIdx.x < HEADS) {
        g_ymol[m * HEADS + threadIdx.x] =
            swarp[0][threadIdx.x] + swarp[1][threadIdx.x]
          + swarp[2][threadIdx.x] + swarp[3][threadIdx.x];
    }
}

// ---------------------------------------------------------------------------
// Kernel 3: batch head.  y[b] = elu((0.001*sum_mol ymol) @ W1 + b1) @ W2 + b2
// ---------------------------------------------------------------------------
__global__ void final_kernel(const float* __restrict__ W1, const float* __restrict__ b1,
                             const float* __restrict__ W2, const float* __restrict__ b2,
                             float* __restrict__ out_y)
{
    int b = threadIdx.x;
    if (b >= BATCH) return;
    float y[HEADS];
    #pragma unroll
    for (int h = 0; h < HEADS; h++) y[h] = 0.f;
    for (int m = 0; m < MOLA; m++) {
        #pragma unroll
        for (int h = 0; h < HEADS; h++)
            y[h] += g_ymol[(b * MOLA + m) * HEADS + h];
    }
    #pragma unroll
    for (int h = 0; h < HEADS; h++) y[h] *= 0.001f;

    float outv = b2[0];
    #pragma unroll
    for (int j = 0; j < 2 * HEADS; j++) {
        float t = b1[j];
        #pragma unroll
        for (int h = 0; h < HEADS; h++)
            t = fmaf(y[h], W1[h * (2 * HEADS) + j], t);
        t = (t > 0.f) ? t : expm1f(t);           // plain elu (64 calls, keep precise)
        outv = fmaf(t, W2[j], outv);
    }
    out_y[b] = outv;
}

// ---------------------------------------------------------------------------
// Launch. Inputs (metadata order): mol_feats, pro_feats, spatial_feats,
// W_sigma, b_sigma, W_mu, b_mu, W1, b1, W2, b2, mol_index, pro_index, mol_batch.
// Indices are fully structured -> computed arithmetically, never read.
// Output: [mu (P*8) | sigma (P*8) | y (64)] float32.
// ---------------------------------------------------------------------------
extern "C" void kernel_launch(void* const* d_in, const int* in_sizes, int n_in,
                              void* d_out, int out_size)
{
    const float* mol_feats = (const float*)d_in[0];
    const float* pro_feats = (const float*)d_in[1];
    const float* spat      = (const float*)d_in[2];
    const float* Wsig      = (const float*)d_in[3];
    const float* bsig      = (const float*)d_in[4];
    const float* Wmu       = (const float*)d_in[5];
    const float* bmu       = (const float*)d_in[6];
    const float* W1        = (const float*)d_in[7];
    const float* b1        = (const float*)d_in[8];
    const float* W2        = (const float*)d_in[9];
    const float* b2        = (const float*)d_in[10];

    float* out_mu  = (float*)d_out;
    float* out_sig = out_mu + NPAIR * HEADS;
    float* out_y   = out_mu + 2 * NPAIR * HEADS;

    const int rows = NMOL + NPRO;
    proj_kernel<<<(rows + 255) / 256, 256>>>(mol_feats, pro_feats, spat,
                                             Wsig, bsig, Wmu, bmu);
    pairs_kernel<<<NMOL, PAIR_THREADS>>>(out_mu, out_sig);
    final_kernel<<<1, BATCH>>>(W1, b1, W2, b2, out_y);
}